// round 13
// baseline (speedup 1.0000x reference)
#include <cuda_runtime.h>
#include <cuda_fp16.h>

#define N_NODES 12288
#define DIM 64
#define N_EDGES 262144
#define EPS_F 0.01f

// Repacked storage: r rows compressed to fp16 (64 halfs = 128B = ONE cache
// line per row); per-edge exp(-m) pairs precomputed in the pre-pass.
__device__ __half g_rh[N_NODES * DIM];
__device__ float2 g_xe[N_EDGES];   // {exp(-m_u), exp(-m_v)} per edge

// Pre-pass, 262144 threads:
//  - t < 196608: repack 4 r-elements to fp16 (4 coalesced LDG + 1 STG.64)
//  - all t:      gather this edge's (m_u, m_v), store {exp(-m_u), exp(-m_v)}.
// Random gathers + MUFU exp live HERE (latency-slack kernel).
__global__ void __launch_bounds__(256) repack_kernel(
        const float* __restrict__ z,
        const int* __restrict__ eidx) {
    int t = blockIdx.x * blockDim.x + threadIdx.x;
    const int quads = N_NODES * DIM / 4;   // 196608

    if (t < N_EDGES) {
        int u = eidx[t];
        int v = eidx[N_EDGES + t];
        float mu = z[u * 65 + 64];
        float mv = z[v * 65 + 64];
        g_xe[t] = make_float2(__expf(-mu), __expf(-mv));
    }

    if (t < quads) {
        int row = t >> 4;          // 16 quads per 64-wide row
        int col = (t & 15) << 2;
        const float* src = z + row * 65 + col;
        float x0 = src[0];
        float x1 = src[1];
        float x2 = src[2];
        float x3 = src[3];
        __half2 h0 = __floats2half2_rn(x0, x1);
        __half2 h1 = __floats2half2_rn(x2, x3);
        uint2 w;
        w.x = *reinterpret_cast<unsigned*>(&h0);
        w.y = *reinterpret_cast<unsigned*>(&h1);
        *reinterpret_cast<uint2*>(g_rh + (size_t)t * 4) = w;
    }
}

// Accumulate ||a-b||^2 contribution of one 16B chunk (8 halfs), fp32 math
// (proven R8 inner-loop form: convert both operands, subtract in fp32).
__device__ __forceinline__ float sq_chunk(const uint4& pa, const uint4& pb) {
    const __half2* ha = reinterpret_cast<const __half2*>(&pa);
    const __half2* hb = reinterpret_cast<const __half2*>(&pb);
    float acc = 0.0f;
    #pragma unroll
    for (int k = 0; k < 4; k++) {
        float2 fa = __half22float2(ha[k]);
        float2 fb = __half22float2(hb[k]);
        float dx = fa.x - fb.x;
        float dy = fa.y - fb.y;
        acc = fmaf(dx, dx, acc);
        acc = fmaf(dy, dy, acc);
    }
    return acc;
}

// 8 lanes per group, 2 edges per thread (R6 chassis). fp16 rows: one
// LDG.128 wavefront per row. Tail uses the compressed algebra:
//   E = (d2+eps)^l = exp(l*log(d2+eps));  x = E*exp(-m_v);  y = E*exp(-m_u)
//   D = (1+x)(1+y); r = 1/D
//   p_pb = r; p_pu = y*r; p_nu = x*r; p_nb = x*y*r
// -> 3 MUFU per edge instead of 5, ~11 FMA ops instead of ~17.
__global__ void __launch_bounds__(256) edge_kernel(
        const int* __restrict__ eidx,
        const float* __restrict__ lptr,
        float4* __restrict__ out) {
    unsigned tid = blockIdx.x * blockDim.x + threadIdx.x;
    unsigned g = tid >> 3;            // group id: handles edges 2g, 2g+1
    unsigned i = tid & 7u;
    unsigned e0 = 2u * g;
    if (e0 >= N_EDGES) return;
    unsigned e1 = e0 + 1u;

    // Merged index loads (LDG.64) + coalesced exp(-m) pair load (LDG.128).
    int2 uu = *reinterpret_cast<const int2*>(eidx + e0);
    int2 vv = *reinterpret_cast<const int2*>(eidx + N_EDGES + e0);
    float4 xm = *reinterpret_cast<const float4*>(g_xe + e0);
    // xm = {e_mu0, e_mv0, e_mu1, e_mv1}

    const uint4* __restrict__ rb = reinterpret_cast<const uint4*>(g_rh);

    // Payload: 4 independent LDG.128 (one full 128B row each).
    uint4 pa0 = rb[uu.x * 8 + i];
    uint4 pb0 = rb[vv.x * 8 + i];
    uint4 pa1 = rb[uu.y * 8 + i];
    uint4 pb1 = rb[vv.y * 8 + i];

    float acc0 = sq_chunk(pa0, pb0);
    float acc1 = sq_chunk(pa1, pb1);

    // Interleaved 3-step reduces across the 8-lane group.
    acc0 += __shfl_xor_sync(0xffffffffu, acc0, 4);
    acc1 += __shfl_xor_sync(0xffffffffu, acc1, 4);
    acc0 += __shfl_xor_sync(0xffffffffu, acc0, 2);
    acc1 += __shfl_xor_sync(0xffffffffu, acc1, 2);
    acc0 += __shfl_xor_sync(0xffffffffu, acc0, 1);
    acc1 += __shfl_xor_sync(0xffffffffu, acc1, 1);

    if (i == 0) {
        float l = __ldg(lptr);

        float E0 = __expf(l * __logf(acc0 + EPS_F));  // (d2+eps)^l
        float E1 = __expf(l * __logf(acc1 + EPS_F));

        float x0 = E0 * xm.y;   // exp(-logit_uv0) = E0 * exp(-m_v0)
        float y0 = E0 * xm.x;   // exp(-logit_vu0) = E0 * exp(-m_u0)
        float x1 = E1 * xm.w;
        float y1 = E1 * xm.z;

        float r0 = __fdividef(1.0f, (1.0f + x0) * (1.0f + y0));
        float r1 = __fdividef(1.0f, (1.0f + x1) * (1.0f + y1));

        float4 o0, o1;
        o0.x = x0 * y0 * r0;   // p_nb
        o0.y = y0 * r0;        // p_pu = suv*(1-svu)
        o0.z = r0;             // p_pb
        o0.w = x0 * r0;        // p_nu
        o1.x = x1 * y1 * r1;
        o1.y = y1 * r1;
        o1.z = r1;
        o1.w = x1 * r1;
        out[e0] = o0;
        out[e1] = o1;
    }
}

extern "C" void kernel_launch(void* const* d_in, const int* in_sizes, int n_in,
                              void* d_out, int out_size) {
    const float* z    = (const float*)d_in[0];
    const float* l    = (const float*)d_in[1];
    const int*   eidx = (const int*)d_in[2];   // int64 in reference, but JAX
                                               // x64 is disabled -> int32
    float4*      out  = (float4*)d_out;

    // Repack + per-edge exp(-m) gather: 262144 threads
    {
        int threads = 256;
        int blocks = (N_EDGES + threads - 1) / threads;
        repack_kernel<<<blocks, threads>>>(z, eidx);
    }

    // Edge kernel: 8 threads per 2 edges -> N_EDGES*4 = 1,048,576 threads
    {
        int threads = 256;
        long long total = (long long)N_EDGES * 4;
        int blocks = (int)((total + threads - 1) / threads);
        edge_kernel<<<blocks, threads>>>(eidx, l, out);
    }
}

// round 14
// speedup vs baseline: 1.1102x; 1.1102x over previous
#include <cuda_runtime.h>
#include <cuda_fp16.h>

#define N_NODES 12288
#define DIM 64
#define N_EDGES 262144
#define EPS_F 0.01f

// Repacked storage: r rows compressed to fp16 (64 halfs = 128B = ONE cache
// line per row); per-edge exp(-m) pairs precomputed in the pre-pass.
__device__ __half g_rh[N_NODES * DIM];
__device__ float2 g_xe[N_EDGES];   // {exp(-m_u), exp(-m_v)} per edge

// Pre-pass, 262144 threads:
//  - t < 196608: repack 4 r-elements to fp16 (4 coalesced LDG + 1 STG.64)
//  - all t:      gather this edge's (m_u, m_v), store {exp(-m_u), exp(-m_v)}.
// Random gathers + MUFU exp live HERE (latency-slack kernel).
__global__ void __launch_bounds__(256) repack_kernel(
        const float* __restrict__ z,
        const int* __restrict__ eidx) {
    int t = blockIdx.x * blockDim.x + threadIdx.x;
    const int quads = N_NODES * DIM / 4;   // 196608

    if (t < N_EDGES) {
        int u = eidx[t];
        int v = eidx[N_EDGES + t];
        float mu = z[u * 65 + 64];
        float mv = z[v * 65 + 64];
        g_xe[t] = make_float2(__expf(-mu), __expf(-mv));
    }

    if (t < quads) {
        int row = t >> 4;          // 16 quads per 64-wide row
        int col = (t & 15) << 2;
        const float* src = z + row * 65 + col;
        float x0 = src[0];
        float x1 = src[1];
        float x2 = src[2];
        float x3 = src[3];
        __half2 h0 = __floats2half2_rn(x0, x1);
        __half2 h1 = __floats2half2_rn(x2, x3);
        uint2 w;
        w.x = *reinterpret_cast<unsigned*>(&h0);
        w.y = *reinterpret_cast<unsigned*>(&h1);
        *reinterpret_cast<uint2*>(g_rh + (size_t)t * 4) = w;
    }
}

// Accumulate ||a-b||^2 contribution of one 16B chunk (8 halfs), fp32 math
// (proven R8 inner-loop form: convert both operands, subtract in fp32).
__device__ __forceinline__ float sq_chunk(const uint4& pa, const uint4& pb) {
    const __half2* ha = reinterpret_cast<const __half2*>(&pa);
    const __half2* hb = reinterpret_cast<const __half2*>(&pb);
    float acc = 0.0f;
    #pragma unroll
    for (int k = 0; k < 4; k++) {
        float2 fa = __half22float2(ha[k]);
        float2 fb = __half22float2(hb[k]);
        float dx = fa.x - fb.x;
        float dy = fa.y - fb.y;
        acc = fmaf(dx, dx, acc);
        acc = fmaf(dy, dy, acc);
    }
    return acc;
}

// Warp owns 32 consecutive edges, processed as 4 rounds of 8 (8-lane groups,
// 2 edges/thread per round — the proven payload engine). The xor-butterfly
// reduce leaves the full sum in ALL lanes of each group, so 2 shfls per
// round scatter the 8 accs into lanes 8r..8r+7 (predicated, branch-free).
// After 4 rounds lane j owns edge base+j: ONE fully-active, divergence-free
// tail (coalesced xe load, 3 MUFU, coalesced float4 store) per 32 edges.
__global__ void __launch_bounds__(256) edge_kernel(
        const int* __restrict__ eidx,
        const float* __restrict__ lptr,
        float4* __restrict__ out) {
    unsigned tid  = blockIdx.x * blockDim.x + threadIdx.x;
    unsigned warp = tid >> 5;
    unsigned lane = tid & 31u;
    unsigned base = warp * 32u;        // first of this warp's 32 edges
    unsigned i    = lane & 7u;         // lane within 8-group
    unsigned grp  = lane >> 3;         // group 0..3

    const uint4* __restrict__ rb = reinterpret_cast<const uint4*>(g_rh);
    float l = __ldg(lptr);
    float myacc = 0.0f;

    #pragma unroll
    for (unsigned r = 0; r < 4; r++) {
        unsigned e0 = base + r * 8u + grp * 2u;

        // Merged index loads (uniform within group, 1 wf across warp).
        int2 uu = *reinterpret_cast<const int2*>(eidx + e0);
        int2 vv = *reinterpret_cast<const int2*>(eidx + N_EDGES + e0);

        // Payload: 4 independent LDG.128 (one full 128B row each).
        uint4 pa0 = rb[uu.x * 8 + i];
        uint4 pb0 = rb[vv.x * 8 + i];
        uint4 pa1 = rb[uu.y * 8 + i];
        uint4 pb1 = rb[vv.y * 8 + i];

        float acc0 = sq_chunk(pa0, pb0);
        float acc1 = sq_chunk(pa1, pb1);

        // Butterfly reduce: all 8 lanes of the group end with the full sum.
        acc0 += __shfl_xor_sync(0xffffffffu, acc0, 4);
        acc1 += __shfl_xor_sync(0xffffffffu, acc1, 4);
        acc0 += __shfl_xor_sync(0xffffffffu, acc0, 2);
        acc1 += __shfl_xor_sync(0xffffffffu, acc1, 2);
        acc0 += __shfl_xor_sync(0xffffffffu, acc0, 1);
        acc1 += __shfl_xor_sync(0xffffffffu, acc1, 1);

        // Scatter this round's 8 edge-sums into lanes 8r..8r+7.
        // Dest lane L (grp==r) owns edge j = L&7 of this round:
        //   source group = j>>1, any lane of it (use its lane 0);
        //   acc0 if j even, acc1 if j odd.
        unsigned src = (i >> 1) << 3;
        float va = __shfl_sync(0xffffffffu, acc0, src);
        float vb = __shfl_sync(0xffffffffu, acc1, src);
        float val = (i & 1u) ? vb : va;
        if (grp == r) myacc = val;     // predicated select, no branch
    }

    // Fully-active tail: lane j handles edge base+j.
    unsigned e = base + lane;
    float2 xe = g_xe[e];               // coalesced LDG.64

    float E = __expf(l * __logf(myacc + EPS_F));   // (d2+eps)^l
    float x = E * xe.y;                // exp(-logit_uv) = E*exp(-m_v)
    float y = E * xe.x;                // exp(-logit_vu) = E*exp(-m_u)
    float rr = __fdividef(1.0f, (1.0f + x) * (1.0f + y));

    float4 o;
    o.x = x * y * rr;   // p_nb
    o.y = y * rr;       // p_pu
    o.z = rr;           // p_pb
    o.w = x * rr;       // p_nu
    out[e] = o;         // coalesced STG.128
}

extern "C" void kernel_launch(void* const* d_in, const int* in_sizes, int n_in,
                              void* d_out, int out_size) {
    const float* z    = (const float*)d_in[0];
    const float* l    = (const float*)d_in[1];
    const int*   eidx = (const int*)d_in[2];   // int64 in reference, but JAX
                                               // x64 is disabled -> int32
    float4*      out  = (float4*)d_out;

    // Repack + per-edge exp(-m) gather: 262144 threads
    {
        int threads = 256;
        int blocks = (N_EDGES + threads - 1) / threads;
        repack_kernel<<<blocks, threads>>>(z, eidx);
    }

    // Edge kernel: 32 edges per warp -> 8192 warps -> 1024 blocks of 256.
    {
        int threads = 256;
        int warps = N_EDGES / 32;
        int blocks = warps / (threads / 32);
        edge_kernel<<<blocks, threads>>>(eidx, l, out);
    }
}

// round 15
// speedup vs baseline: 1.2850x; 1.1575x over previous
#include <cuda_runtime.h>
#include <cuda_fp16.h>

#define N_NODES 12288
#define DIM 64
#define N_EDGES 262144
#define EPS_F 0.01f

// Repacked storage: r rows compressed to fp16 (64 halfs = 128B = ONE cache
// line per row); per-NODE exp(-m) table (48KB, L1-resident in edge kernel).
__device__ __half g_rh[N_NODES * DIM];
__device__ float  g_xn[N_NODES];   // exp(-m[node])

// Pre-pass, 196608 threads: pure transpose (4 coalesced LDG + 1 STG.64 each)
// + per-node exp(-m) (12288 of them). No random gathers here anymore.
__global__ void __launch_bounds__(256) repack_kernel(const float* __restrict__ z) {
    int t = blockIdx.x * blockDim.x + threadIdx.x;
    const int quads = N_NODES * DIM / 4;   // 196608

    if (t < quads) {
        int row = t >> 4;          // 16 quads per 64-wide row
        int col = (t & 15) << 2;
        const float* src = z + row * 65 + col;
        float x0 = src[0];
        float x1 = src[1];
        float x2 = src[2];
        float x3 = src[3];
        __half2 h0 = __floats2half2_rn(x0, x1);
        __half2 h1 = __floats2half2_rn(x2, x3);
        uint2 w;
        w.x = *reinterpret_cast<unsigned*>(&h0);
        w.y = *reinterpret_cast<unsigned*>(&h1);
        *reinterpret_cast<uint2*>(g_rh + (size_t)t * 4) = w;
    }
    if (t < N_NODES) {
        g_xn[t] = __expf(-z[t * 65 + 64]);
    }
}

// Accumulate ||a-b||^2 contribution of one 16B chunk (8 halfs), fp32 math
// (proven R8 inner-loop form: convert both operands, subtract in fp32).
__device__ __forceinline__ float sq_chunk(const uint4& pa, const uint4& pb) {
    const __half2* ha = reinterpret_cast<const __half2*>(&pa);
    const __half2* hb = reinterpret_cast<const __half2*>(&pb);
    float acc = 0.0f;
    #pragma unroll
    for (int k = 0; k < 4; k++) {
        float2 fa = __half22float2(ha[k]);
        float2 fb = __half22float2(hb[k]);
        float dx = fa.x - fb.x;
        float dy = fa.y - fb.y;
        acc = fmaf(dx, dx, acc);
        acc = fmaf(dy, dy, acc);
    }
    return acc;
}

// Warp owns 32 consecutive edges, processed as 4 rounds of 8 (8-lane groups,
// 2 edges/thread per round). The xor-butterfly reduce leaves the full sum in
// all lanes of each group; 2 shfls/round scatter the 8 sums into lanes
// 8r..8r+7 (branch-free). Tail is fully active: lane j owns edge base+j.
// The tail's exp(-m) gathers are issued in the PROLOGUE (edge indices are
// coalesced) so their ~L2 latency is covered by the 4 compute rounds.
__global__ void __launch_bounds__(256) edge_kernel(
        const int* __restrict__ eidx,
        const float* __restrict__ lptr,
        float4* __restrict__ out) {
    unsigned tid  = blockIdx.x * blockDim.x + threadIdx.x;
    unsigned warp = tid >> 5;
    unsigned lane = tid & 31u;
    unsigned base = warp * 32u;        // first of this warp's 32 edges
    unsigned i    = lane & 7u;         // lane within 8-group
    unsigned grp  = lane >> 3;         // group 0..3

    const uint4* __restrict__ rb = reinterpret_cast<const uint4*>(g_rh);
    float l = __ldg(lptr);

    // Prologue: my tail edge's node indices (coalesced) + exp(-m) gathers,
    // issued now and consumed ~2000 cycles later in the tail.
    unsigned e_mine = base + lane;
    int u_mine = eidx[e_mine];
    int v_mine = eidx[N_EDGES + e_mine];
    float xu = g_xn[u_mine];           // random gather into 48KB L1-hot table
    float xv = g_xn[v_mine];

    float myacc = 0.0f;

    #pragma unroll
    for (unsigned r = 0; r < 4; r++) {
        unsigned e0 = base + r * 8u + grp * 2u;

        // Merged index loads (uniform within group).
        int2 uu = *reinterpret_cast<const int2*>(eidx + e0);
        int2 vv = *reinterpret_cast<const int2*>(eidx + N_EDGES + e0);

        // Payload: 4 independent LDG.128 (one full 128B row each).
        uint4 pa0 = rb[uu.x * 8 + i];
        uint4 pb0 = rb[vv.x * 8 + i];
        uint4 pa1 = rb[uu.y * 8 + i];
        uint4 pb1 = rb[vv.y * 8 + i];

        float acc0 = sq_chunk(pa0, pb0);
        float acc1 = sq_chunk(pa1, pb1);

        // Butterfly reduce: all 8 lanes of the group end with the full sum.
        acc0 += __shfl_xor_sync(0xffffffffu, acc0, 4);
        acc1 += __shfl_xor_sync(0xffffffffu, acc1, 4);
        acc0 += __shfl_xor_sync(0xffffffffu, acc0, 2);
        acc1 += __shfl_xor_sync(0xffffffffu, acc1, 2);
        acc0 += __shfl_xor_sync(0xffffffffu, acc0, 1);
        acc1 += __shfl_xor_sync(0xffffffffu, acc1, 1);

        // Scatter this round's 8 edge-sums into lanes 8r..8r+7.
        unsigned src = (i >> 1) << 3;
        float va = __shfl_sync(0xffffffffu, acc0, src);
        float vb = __shfl_sync(0xffffffffu, acc1, src);
        float val = (i & 1u) ? vb : va;
        if (grp == r) myacc = val;     // predicated select, no branch
    }

    // Fully-active tail: lane j handles edge base+j.
    float E = __expf(l * __logf(myacc + EPS_F));   // (d2+eps)^l
    float x = E * xv;                  // exp(-logit_uv) = E*exp(-m_v)
    float y = E * xu;                  // exp(-logit_vu) = E*exp(-m_u)
    float rr = __fdividef(1.0f, (1.0f + x) * (1.0f + y));

    float4 o;
    o.x = x * y * rr;   // p_nb
    o.y = y * rr;       // p_pu
    o.z = rr;           // p_pb
    o.w = x * rr;       // p_nu
    out[e_mine] = o;    // coalesced STG.128
}

extern "C" void kernel_launch(void* const* d_in, const int* in_sizes, int n_in,
                              void* d_out, int out_size) {
    const float* z    = (const float*)d_in[0];
    const float* l    = (const float*)d_in[1];
    const int*   eidx = (const int*)d_in[2];   // int64 in reference, but JAX
                                               // x64 is disabled -> int32
    float4*      out  = (float4*)d_out;

    // Repack (transpose + per-node exp): 196608 threads
    {
        int threads = 256;
        int quads = N_NODES * DIM / 4;
        int blocks = (quads + threads - 1) / threads;
        repack_kernel<<<blocks, threads>>>(z);
    }

    // Edge kernel: 32 edges per warp -> 8192 warps -> 1024 blocks of 256.
    {
        int threads = 256;
        int warps = N_EDGES / 32;
        int blocks = warps / (threads / 32);
        edge_kernel<<<blocks, threads>>>(eidx, l, out);
    }
}